// round 11
// baseline (speedup 1.0000x reference)
#include <cuda_runtime.h>
#include <cstdint>

#define D     512
#define LSEQ  8192
#define BATCH 8
#define NROWS (BATCH*LSEQ)   // 65536

// Output layout (float32, tuple order):
#define OFF_COMP 0ull
#define OFF_MASK 33554432ull            // B*L*D
#define OFF_BH   (OFF_MASK + 65536ull)
#define OFF_P    (OFF_BH   + 65536ull)
#define OFF_PC   (OFF_P    + 65536ull)
#define OFF_LOSS (OFF_PC   + 65536ull)

#define FLAG_CAP 8192

// GEMM tiling
#define SA        20                  // smem row stride in floats (bank-conflict pad)
#define KC        16
#define NSTG      (D/KC)              // 32 k-stages
#define A_F       (129*SA)            // A tile: 129 rows (halo row m0-1)
#define B_F       (256*SA)            // B tile: Wq 128 rows + Wk 128 rows
#define SLOT_F    (A_F + B_F)         // 7700 floats
#define DYN_SMEM  (3*SLOT_F*4)        // 92400 bytes

// ---- scratch (static device arrays: no allocation) ----
__device__ float g_pnum[8][NROWS];    // per (echunk,wn) partial q·k_prev
__device__ float g_pnq [8][NROWS];    // partial |q|^2
__device__ float g_pnk [8][NROWS];    // partial |k_prev|^2
__device__ float g_p[NROWS];
__device__ int   g_pos[NROWS];
__device__ int   g_cnt[BATCH];
__device__ float g_bsum[BATCH * 2];
__device__ int   g_flag_cnt;
__device__ int   g_flagr[FLAG_CAP];
__device__ float g_flagrs[FLAG_CAP];
__device__ float g_fixp[2][FLAG_CAP];  // per-e-slice exact partial of q·k_prev

// ============================ helpers ============================
__device__ __forceinline__ uint32_t smem_u32(const void* p) {
    uint32_t a;
    asm("{ .reg .u64 t; cvta.to.shared.u64 t, %1; cvt.u32.u64 %0, t; }" : "=r"(a) : "l"(p));
    return a;
}
__device__ __forceinline__ void cpasync16(uint32_t daddr, const void* gp) {
    asm volatile("cp.async.cg.shared.global [%0], [%1], 16;" :: "r"(daddr), "l"(gp) : "memory");
}
__device__ __forceinline__ void mma_tf32(float* c, const uint32_t* a, const uint32_t* b) {
    asm volatile(
        "mma.sync.aligned.m16n8k8.row.col.f32.tf32.tf32.f32 "
        "{%0,%1,%2,%3}, {%4,%5,%6,%7}, {%8,%9}, {%0,%1,%2,%3};"
        : "+f"(c[0]), "+f"(c[1]), "+f"(c[2]), "+f"(c[3])
        : "r"(a[0]), "r"(a[1]), "r"(a[2]), "r"(a[3]), "r"(b[0]), "r"(b[1]));
}

// ============================ Kernel 0: zero flag counter ============================
__global__ void zero_kernel() { g_flag_cnt = 0; }

// ============================ Kernel 1: fused TF32 GEMM + row reductions ============
__global__ __launch_bounds__(256, 1)
void gemm_fused_kernel(const float* __restrict__ x,
                       const float* __restrict__ Wq,
                       const float* __restrict__ Wk) {
    extern __shared__ float sm[];
    const int tid  = threadIdx.x;
    const int w    = tid >> 5, lane = tid & 31;
    const int wm   = w >> 1, wn = w & 1;
    const int g    = lane >> 2, t = lane & 3;
    const int ec   = blockIdx.x;            // 0..3
    const int m0   = blockIdx.y * 128;
    const int e0   = ec * 128;

    float accq[2][8][4], acck[2][8][4];
    #pragma unroll
    for (int mi = 0; mi < 2; mi++)
        #pragma unroll
        for (int ni = 0; ni < 8; ni++)
            #pragma unroll
            for (int r = 0; r < 4; r++) { accq[mi][ni][r] = 0.f; acck[mi][ni][r] = 0.f; }

    const uint32_t smu = smem_u32(sm);

    auto issue = [&](int s, int slot) {
        const uint32_t sb = smu + (uint32_t)slot * SLOT_F * 4;
        const int k0 = s * KC;
        #pragma unroll
        for (int it = 0; it < 3; it++) {
            int c = it * 256 + tid;
            if (c < 516) {
                int row = c >> 2, c4 = c & 3;
                int gr = m0 - 1 + row; if (gr < 0) gr = 0;
                cpasync16(sb + (uint32_t)(row * SA + c4 * 4) * 4,
                          x + (size_t)gr * D + k0 + c4 * 4);
            }
        }
        #pragma unroll
        for (int it = 0; it < 4; it++) {
            int c = it * 256 + tid;
            int row = c >> 2, c4 = c & 3;
            const float* src = (row < 128) ? (Wq + (size_t)(e0 + row) * D)
                                           : (Wk + (size_t)(e0 + row - 128) * D);
            cpasync16(sb + (uint32_t)(A_F + row * SA + c4 * 4) * 4,
                      src + k0 + c4 * 4);
        }
        asm volatile("cp.async.commit_group;" ::: "memory");
    };

    issue(0, 0);
    issue(1, 1);

    for (int s = 0; s < NSTG; s++) {
        if (s + 2 < NSTG) issue(s + 2, (s + 2) % 3);
        else asm volatile("cp.async.commit_group;" ::: "memory");
        asm volatile("cp.async.wait_group 2;" ::: "memory");
        __syncthreads();

        const float* As = sm + (s % 3) * SLOT_F;
        const float* Bs = As + A_F;

        #pragma unroll
        for (int k8 = 0; k8 < 2; k8++) {
            const int kk = k8 * 8;
            uint32_t aq[2][4], ak[2][4];
            #pragma unroll
            for (int mi = 0; mi < 2; mi++) {
                int r0 = wm * 32 + mi * 16 + g;          // local (row+1 = Q row)
                aq[mi][0] = __float_as_uint(As[(r0 + 1) * SA + kk + t    ]);
                aq[mi][1] = __float_as_uint(As[(r0 + 9) * SA + kk + t    ]);
                aq[mi][2] = __float_as_uint(As[(r0 + 1) * SA + kk + t + 4]);
                aq[mi][3] = __float_as_uint(As[(r0 + 9) * SA + kk + t + 4]);
                ak[mi][0] = __float_as_uint(As[(r0    ) * SA + kk + t    ]);
                ak[mi][1] = __float_as_uint(As[(r0 + 8) * SA + kk + t    ]);
                ak[mi][2] = __float_as_uint(As[(r0    ) * SA + kk + t + 4]);
                ak[mi][3] = __float_as_uint(As[(r0 + 8) * SA + kk + t + 4]);
            }
            uint32_t bq[8][2], bk[8][2];
            #pragma unroll
            for (int ni = 0; ni < 8; ni++) {
                int e = wn * 64 + ni * 8 + g;
                bq[ni][0] = __float_as_uint(Bs[(e      ) * SA + kk + t    ]);
                bq[ni][1] = __float_as_uint(Bs[(e      ) * SA + kk + t + 4]);
                bk[ni][0] = __float_as_uint(Bs[(128 + e) * SA + kk + t    ]);
                bk[ni][1] = __float_as_uint(Bs[(128 + e) * SA + kk + t + 4]);
            }
            #pragma unroll
            for (int mi = 0; mi < 2; mi++)
                #pragma unroll
                for (int ni = 0; ni < 8; ni++) {
                    mma_tf32(accq[mi][ni], aq[mi], bq[ni]);
                    mma_tf32(acck[mi][ni], ak[mi], bk[ni]);
                }
        }
        __syncthreads();
    }

    // Fused epilogue: per-row partial reductions over this warp's 64 cols.
    const int slot = ec * 2 + wn;
    #pragma unroll
    for (int mi = 0; mi < 2; mi++) {
        float pn0 = 0.f, pq0 = 0.f, pk0 = 0.f;
        float pn1 = 0.f, pq1 = 0.f, pk1 = 0.f;
        #pragma unroll
        for (int ni = 0; ni < 8; ni++) {
            float q0 = accq[mi][ni][0], q1 = accq[mi][ni][1];
            float q2 = accq[mi][ni][2], q3 = accq[mi][ni][3];
            float k0v = acck[mi][ni][0], k1v = acck[mi][ni][1];
            float k2v = acck[mi][ni][2], k3v = acck[mi][ni][3];
            pn0 += q0 * k0v + q1 * k1v;
            pq0 += q0 * q0 + q1 * q1;
            pk0 += k0v * k0v + k1v * k1v;
            pn1 += q2 * k2v + q3 * k3v;
            pq1 += q2 * q2 + q3 * q3;
            pk1 += k2v * k2v + k3v * k3v;
        }
        #pragma unroll
        for (int m = 1; m <= 2; m <<= 1) {
            pn0 += __shfl_xor_sync(0xffffffffu, pn0, m);
            pq0 += __shfl_xor_sync(0xffffffffu, pq0, m);
            pk0 += __shfl_xor_sync(0xffffffffu, pk0, m);
            pn1 += __shfl_xor_sync(0xffffffffu, pn1, m);
            pq1 += __shfl_xor_sync(0xffffffffu, pq1, m);
            pk1 += __shfl_xor_sync(0xffffffffu, pk1, m);
        }
        if (t == 0) {
            int r = m0 + wm * 32 + mi * 16 + g;
            g_pnum[slot][r]     = pn0; g_pnq[slot][r]     = pq0; g_pnk[slot][r]     = pk0;
            g_pnum[slot][r + 8] = pn1; g_pnq[slot][r + 8] = pq1; g_pnk[slot][r + 8] = pk1;
        }
    }
}

// ============================ Kernel 2: finalize cos / p / flag ============================
__global__ __launch_bounds__(256)
void cosfin_kernel() {
    const int r = blockIdx.x * 256 + threadIdx.x;
    float num = 0.f, nq = 0.f, nk = 0.f;
    #pragma unroll
    for (int s = 0; s < 8; s++) {
        num += g_pnum[s][r]; nq += g_pnq[s][r]; nk += g_pnk[s][r];
    }
    const int l = r & (LSEQ - 1);
    float rs = rsqrtf(nq * nk);
    float cs = num * rs;
    float p = fminf(fmaxf(0.5f * (1.f - cs), 0.f), 1.f);
    if (l == 0) p = 1.f;
    g_p[r] = p;
    if (l != 0 && fabsf(cs) < 3e-4f) {
        int i = atomicAdd(&g_flag_cnt, 1);
        if (i < FLAG_CAP) { g_flagr[i] = r; g_flagrs[i] = rs; }
    }
}

// ============================ Kernel 3: batched exact fp32 recompute (partials) =====
// grid (2 e-slices, 64 row-chunk slots). Each block: 8 flagged pairs in smem,
// streams its 256-row W slice ONCE per chunk; per-row exact partial q·k_prev
// -> g_fixp[slice][i] (unique writer, deterministic reduction order).
__global__ __launch_bounds__(256)
void fixpart_kernel(const float* __restrict__ x,
                    const float* __restrict__ Wq, const float* __restrict__ Wk) {
    __shared__ float4 xs[8][128], xps[8][128];
    __shared__ float  red[256];
    const int tid = threadIdx.x;
    const int e   = blockIdx.x * 256 + tid;       // this thread's W row
    int cnt = g_flag_cnt; if (cnt > FLAG_CAP) cnt = FLAG_CAP;

    for (int c0 = blockIdx.y * 8; c0 < cnt; c0 += gridDim.y * 8) {
        const int nrows = min(8, cnt - c0);
        for (int idx = tid; idx < nrows * 128; idx += 256) {
            int j = idx >> 7, d4 = idx & 127;
            int r = g_flagr[c0 + j];              // l != 0 guaranteed
            xs [j][d4] = ((const float4*)(x + (size_t)r * D))[d4];
            xps[j][d4] = ((const float4*)(x + (size_t)(r - 1) * D))[d4];
        }
        __syncthreads();

        const float4* wq = (const float4*)(Wq + (size_t)e * D);
        const float4* wk = (const float4*)(Wk + (size_t)e * D);
        float qj[8], kj[8];
        #pragma unroll
        for (int j = 0; j < 8; j++) { qj[j] = 0.f; kj[j] = 0.f; }
        for (int d4 = 0; d4 < 128; d4++) {
            float4 a = wq[d4];
            float4 b = wk[d4];
            #pragma unroll
            for (int j = 0; j < 8; j++) {
                float4 xv = xs[j][d4];             // broadcast LDS
                qj[j] += a.x*xv.x + a.y*xv.y + a.z*xv.z + a.w*xv.w;
                float4 pv = xps[j][d4];
                kj[j] += b.x*pv.x + b.y*pv.y + b.z*pv.z + b.w*pv.w;
            }
        }
        // block-reduce q_j * k_j over the 256 e-values, per row j
        for (int j = 0; j < 8; j++) {
            red[tid] = qj[j] * kj[j];
            __syncthreads();
            for (int o = 128; o > 0; o >>= 1) {
                if (tid < o) red[tid] += red[tid + o];
                __syncthreads();
            }
            if (tid == 0 && j < nrows) g_fixp[blockIdx.x][c0 + j] = red[0];
            __syncthreads();
        }
    }
}

// ============================ Kernel 3b: finalize fixed rows ============================
__global__ __launch_bounds__(256)
void fixfin_kernel() {
    int cnt = g_flag_cnt; if (cnt > FLAG_CAP) cnt = FLAG_CAP;
    for (int i = blockIdx.x * 256 + threadIdx.x; i < cnt; i += gridDim.x * 256) {
        float num = g_fixp[0][i] + g_fixp[1][i];
        g_p[g_flagr[i]] = fminf(fmaxf(0.5f * (1.f - num * g_flagrs[i]), 0.f), 1.f);
    }
}

// ============================ Kernel 4: per-batch scan ============================
__global__ __launch_bounds__(256)
void scan_kernel(float* __restrict__ out) {
    const int b   = blockIdx.x;
    const int tid = threadIdx.x;
    const int PER = LSEQ / 256;            // 32
    const int base = b * LSEQ + tid * PER;

    __shared__ int   sInt[256];
    __shared__ float sF[256];

    float pv[32];
    unsigned bits = 0;
    int localsum = 0;
    float psum = 0.f;

    #pragma unroll
    for (int u = 0; u < PER; u++) {
        int r = base + u;
        float p = g_p[r];
        pv[u] = p;
        int h = (p >= 0.5f) ? 1 : 0;
        bits |= ((unsigned)h) << u;
        localsum += h;
        psum += p;
    }

    sInt[tid] = localsum;
    __syncthreads();
    for (int off = 1; off < 256; off <<= 1) {
        int v = (tid >= off) ? sInt[tid - off] : 0;
        __syncthreads();
        sInt[tid] += v;
        __syncthreads();
    }
    int excl  = sInt[tid] - localsum;
    int total = sInt[255];

    int run = excl;
    #pragma unroll
    for (int u = 0; u < PER; u++) {
        int r = base + u;
        float p = pv[u];
        int h = (bits >> u) & 1;
        out[OFF_P  + r] = p;
        out[OFF_BH + r] = h ? 1.0f : 0.0f;
        g_pos[r] = h ? run : -1;
        run += h;
    }

    sF[tid] = psum;
    __syncthreads();
    for (int off = 128; off > 0; off >>= 1) {
        if (tid < off) sF[tid] += sF[tid + off];
        __syncthreads();
    }
    if (tid == 0) {
        g_cnt[b] = total;
        g_bsum[b * 2 + 0] = (float)total;
        g_bsum[b * 2 + 1] = sF[0];
    }
}

// ============================ Kernel 5: scatter ============================
__global__ __launch_bounds__(128)
void scatter_kernel(const float* __restrict__ x, float* __restrict__ out) {
    const int r   = blockIdx.x;
    const int b   = r >> 13;
    const int l   = r & (LSEQ - 1);
    const int tid = threadIdx.x;

    int pos = g_pos[r];
    if (pos >= 0) {
        float4 v = reinterpret_cast<const float4*>(x + (size_t)r * D)[tid];
        size_t dst = (size_t)(b * LSEQ + pos) * D;
        reinterpret_cast<float4*>(out + OFF_COMP + dst)[tid] = v;
        if (tid == 0) out[OFF_PC + b * LSEQ + pos] = out[OFF_P + r];
    }
    int cnt = g_cnt[b];
    if (l >= cnt) {
        reinterpret_cast<float4*>(out + OFF_COMP + (size_t)r * D)[tid] =
            make_float4(0.f, 0.f, 0.f, 0.f);
        if (tid == 0) { out[OFF_PC + r] = 0.f; out[OFF_MASK + r] = 0.f; }
    } else if (tid == 0) {
        out[OFF_MASK + r] = 1.0f;
    }
}

// ============================ Kernel 6: ratio loss ============================
__global__ void loss_kernel(float* __restrict__ out) {
    float F = 0.f, G = 0.f;
    for (int b = 0; b < BATCH; b++) { F += g_bsum[b*2+0]; G += g_bsum[b*2+1]; }
    F /= (float)NROWS;
    G /= (float)NROWS;
    const float N = 6.0f;
    out[OFF_LOSS] = N / (N - 1.0f) * ((N - 1.0f) * F * G + (1.0f - F) * (1.0f - G));
}

// ============================ launch ============================
extern "C" void kernel_launch(void* const* d_in, const int* in_sizes, int n_in,
                              void* d_out, int out_size) {
    const float* x  = (const float*)d_in[0];
    const float* Wq = (const float*)d_in[1];
    const float* Wk = (const float*)d_in[2];
    float* out = (float*)d_out;

    cudaFuncSetAttribute(gemm_fused_kernel, cudaFuncAttributeMaxDynamicSharedMemorySize, DYN_SMEM);

    zero_kernel<<<1, 1>>>();
    {
        dim3 grid(4, 512);                                  // echunk x mtile
        gemm_fused_kernel<<<grid, 256, DYN_SMEM>>>(x, Wq, Wk);
    }
    cosfin_kernel<<<NROWS / 256, 256>>>();
    {
        dim3 grid(2, 64);                                   // e-slice x row-chunk slot
        fixpart_kernel<<<grid, 256>>>(x, Wq, Wk);
    }
    fixfin_kernel<<<32, 256>>>();
    scan_kernel<<<BATCH, 256>>>(out);
    scatter_kernel<<<NROWS, 128>>>(x, out);
    loss_kernel<<<1, 1>>>(out);
}

// round 12
// speedup vs baseline: 1.5790x; 1.5790x over previous
#include <cuda_runtime.h>
#include <cstdint>

#define D     512
#define LSEQ  8192
#define BATCH 8
#define NROWS (BATCH*LSEQ)   // 65536

// Output layout (float32, tuple order):
#define OFF_COMP 0ull
#define OFF_MASK 33554432ull            // B*L*D
#define OFF_BH   (OFF_MASK + 65536ull)
#define OFF_P    (OFF_BH   + 65536ull)
#define OFF_PC   (OFF_P    + 65536ull)
#define OFF_LOSS (OFF_PC   + 65536ull)

#define FLAG_CAP 8192

// GEMM tiling
#define SA        20                  // smem row stride in floats (bank-conflict pad)
#define KC        16
#define NSTG      (D/KC)              // 32 k-stages
#define A_F       (129*SA)            // A tile: 129 rows (halo row m0-1)
#define B_F       (256*SA)            // B tile: Wq 128 rows + Wk 128 rows
#define SLOT_F    (A_F + B_F)         // 7700 floats
#define DYN_SMEM  (3*SLOT_F*4)        // 92400 bytes

// ---- scratch (static device arrays: no allocation) ----
__device__ float g_pnum[8][NROWS];    // per (echunk,wn) partial q·k_prev
__device__ float g_pnq [8][NROWS];    // partial |q|^2
__device__ float g_pnk [8][NROWS];    // partial |k_prev|^2
__device__ float g_M[512 * 512];      // Wq^T Wk  (1 MB, fp32 exact)
__device__ float g_p[NROWS];
__device__ int   g_pos[NROWS];
__device__ int   g_cnt[BATCH];
__device__ float g_bsum[BATCH * 2];
__device__ int   g_flag_cnt;
__device__ int   g_flagr[FLAG_CAP];
__device__ float g_flagrs[FLAG_CAP];
__device__ float g_fixp[2][FLAG_CAP];  // per-d1-slice exact partial of x_r^T M x_prev

// ============================ helpers ============================
__device__ __forceinline__ uint32_t smem_u32(const void* p) {
    uint32_t a;
    asm("{ .reg .u64 t; cvta.to.shared.u64 t, %1; cvt.u32.u64 %0, t; }" : "=r"(a) : "l"(p));
    return a;
}
__device__ __forceinline__ void cpasync16(uint32_t daddr, const void* gp) {
    asm volatile("cp.async.cg.shared.global [%0], [%1], 16;" :: "r"(daddr), "l"(gp) : "memory");
}
__device__ __forceinline__ void mma_tf32(float* c, const uint32_t* a, const uint32_t* b) {
    asm volatile(
        "mma.sync.aligned.m16n8k8.row.col.f32.tf32.tf32.f32 "
        "{%0,%1,%2,%3}, {%4,%5,%6,%7}, {%8,%9}, {%0,%1,%2,%3};"
        : "+f"(c[0]), "+f"(c[1]), "+f"(c[2]), "+f"(c[3])
        : "r"(a[0]), "r"(a[1]), "r"(a[2]), "r"(a[3]), "r"(b[0]), "r"(b[1]));
}

// ============================ Kernel 0: zero flag counter ============================
__global__ void zero_kernel() { g_flag_cnt = 0; }

// ============================ Kernel 0b: M = Wq^T Wk (fp32, tiled) ============================
// M[d1][d2] = sum_e Wq[e][d1] * Wk[e][d2].  grid (8,8): d2-tile x d1-tile of 64x64.
__global__ __launch_bounds__(256)
void mprep_kernel(const float* __restrict__ Wq, const float* __restrict__ Wk) {
    __shared__ float sq[32][68], sk[32][68];
    const int tid = threadIdx.x;
    const int tx = tid & 15, ty = tid >> 4;
    const int d2_0 = blockIdx.x * 64, d1_0 = blockIdx.y * 64;

    float acc[4][4];
    #pragma unroll
    for (int i = 0; i < 4; i++)
        #pragma unroll
        for (int j = 0; j < 4; j++) acc[i][j] = 0.f;

    for (int e0 = 0; e0 < 512; e0 += 32) {
        #pragma unroll
        for (int it = 0; it < 2; it++) {
            int idx = it * 256 + tid;       // 0..511
            int i = idx >> 4, c4 = idx & 15;
            *(float4*)&sq[i][c4 * 4] = *(const float4*)&Wq[(size_t)(e0 + i) * D + d1_0 + c4 * 4];
            *(float4*)&sk[i][c4 * 4] = *(const float4*)&Wk[(size_t)(e0 + i) * D + d2_0 + c4 * 4];
        }
        __syncthreads();
        #pragma unroll
        for (int e = 0; e < 32; e++) {
            float4 av = *(const float4*)&sq[e][ty * 4];
            float4 bv = *(const float4*)&sk[e][tx * 4];
            float a[4] = {av.x, av.y, av.z, av.w};
            float b[4] = {bv.x, bv.y, bv.z, bv.w};
            #pragma unroll
            for (int i = 0; i < 4; i++)
                #pragma unroll
                for (int j = 0; j < 4; j++) acc[i][j] += a[i] * b[j];
        }
        __syncthreads();
    }
    #pragma unroll
    for (int i = 0; i < 4; i++) {
        float4 v = make_float4(acc[i][0], acc[i][1], acc[i][2], acc[i][3]);
        *(float4*)&g_M[(size_t)(d1_0 + ty * 4 + i) * 512 + d2_0 + tx * 4] = v;
    }
}

// ============================ Kernel 1: fused TF32 GEMM + row reductions ============
__global__ __launch_bounds__(256, 1)
void gemm_fused_kernel(const float* __restrict__ x,
                       const float* __restrict__ Wq,
                       const float* __restrict__ Wk) {
    extern __shared__ float sm[];
    const int tid  = threadIdx.x;
    const int w    = tid >> 5, lane = tid & 31;
    const int wm   = w >> 1, wn = w & 1;
    const int g    = lane >> 2, t = lane & 3;
    const int ec   = blockIdx.x;            // 0..3
    const int m0   = blockIdx.y * 128;
    const int e0   = ec * 128;

    float accq[2][8][4], acck[2][8][4];
    #pragma unroll
    for (int mi = 0; mi < 2; mi++)
        #pragma unroll
        for (int ni = 0; ni < 8; ni++)
            #pragma unroll
            for (int r = 0; r < 4; r++) { accq[mi][ni][r] = 0.f; acck[mi][ni][r] = 0.f; }

    const uint32_t smu = smem_u32(sm);

    auto issue = [&](int s, int slot) {
        const uint32_t sb = smu + (uint32_t)slot * SLOT_F * 4;
        const int k0 = s * KC;
        #pragma unroll
        for (int it = 0; it < 3; it++) {
            int c = it * 256 + tid;
            if (c < 516) {
                int row = c >> 2, c4 = c & 3;
                int gr = m0 - 1 + row; if (gr < 0) gr = 0;
                cpasync16(sb + (uint32_t)(row * SA + c4 * 4) * 4,
                          x + (size_t)gr * D + k0 + c4 * 4);
            }
        }
        #pragma unroll
        for (int it = 0; it < 4; it++) {
            int c = it * 256 + tid;
            int row = c >> 2, c4 = c & 3;
            const float* src = (row < 128) ? (Wq + (size_t)(e0 + row) * D)
                                           : (Wk + (size_t)(e0 + row - 128) * D);
            cpasync16(sb + (uint32_t)(A_F + row * SA + c4 * 4) * 4,
                      src + k0 + c4 * 4);
        }
        asm volatile("cp.async.commit_group;" ::: "memory");
    };

    issue(0, 0);
    issue(1, 1);

    for (int s = 0; s < NSTG; s++) {
        if (s + 2 < NSTG) issue(s + 2, (s + 2) % 3);
        else asm volatile("cp.async.commit_group;" ::: "memory");
        asm volatile("cp.async.wait_group 2;" ::: "memory");
        __syncthreads();

        const float* As = sm + (s % 3) * SLOT_F;
        const float* Bs = As + A_F;

        #pragma unroll
        for (int k8 = 0; k8 < 2; k8++) {
            const int kk = k8 * 8;
            uint32_t aq[2][4], ak[2][4];
            #pragma unroll
            for (int mi = 0; mi < 2; mi++) {
                int r0 = wm * 32 + mi * 16 + g;          // local (row+1 = Q row)
                aq[mi][0] = __float_as_uint(As[(r0 + 1) * SA + kk + t    ]);
                aq[mi][1] = __float_as_uint(As[(r0 + 9) * SA + kk + t    ]);
                aq[mi][2] = __float_as_uint(As[(r0 + 1) * SA + kk + t + 4]);
                aq[mi][3] = __float_as_uint(As[(r0 + 9) * SA + kk + t + 4]);
                ak[mi][0] = __float_as_uint(As[(r0    ) * SA + kk + t    ]);
                ak[mi][1] = __float_as_uint(As[(r0 + 8) * SA + kk + t    ]);
                ak[mi][2] = __float_as_uint(As[(r0    ) * SA + kk + t + 4]);
                ak[mi][3] = __float_as_uint(As[(r0 + 8) * SA + kk + t + 4]);
            }
            uint32_t bq[8][2], bk[8][2];
            #pragma unroll
            for (int ni = 0; ni < 8; ni++) {
                int e = wn * 64 + ni * 8 + g;
                bq[ni][0] = __float_as_uint(Bs[(e      ) * SA + kk + t    ]);
                bq[ni][1] = __float_as_uint(Bs[(e      ) * SA + kk + t + 4]);
                bk[ni][0] = __float_as_uint(Bs[(128 + e) * SA + kk + t    ]);
                bk[ni][1] = __float_as_uint(Bs[(128 + e) * SA + kk + t + 4]);
            }
            #pragma unroll
            for (int mi = 0; mi < 2; mi++)
                #pragma unroll
                for (int ni = 0; ni < 8; ni++) {
                    mma_tf32(accq[mi][ni], aq[mi], bq[ni]);
                    mma_tf32(acck[mi][ni], ak[mi], bk[ni]);
                }
        }
        __syncthreads();
    }

    // Fused epilogue: per-row partial reductions over this warp's 64 cols.
    const int slot = ec * 2 + wn;
    #pragma unroll
    for (int mi = 0; mi < 2; mi++) {
        float pn0 = 0.f, pq0 = 0.f, pk0 = 0.f;
        float pn1 = 0.f, pq1 = 0.f, pk1 = 0.f;
        #pragma unroll
        for (int ni = 0; ni < 8; ni++) {
            float q0 = accq[mi][ni][0], q1 = accq[mi][ni][1];
            float q2 = accq[mi][ni][2], q3 = accq[mi][ni][3];
            float k0v = acck[mi][ni][0], k1v = acck[mi][ni][1];
            float k2v = acck[mi][ni][2], k3v = acck[mi][ni][3];
            pn0 += q0 * k0v + q1 * k1v;
            pq0 += q0 * q0 + q1 * q1;
            pk0 += k0v * k0v + k1v * k1v;
            pn1 += q2 * k2v + q3 * k3v;
            pq1 += q2 * q2 + q3 * q3;
            pk1 += k2v * k2v + k3v * k3v;
        }
        #pragma unroll
        for (int m = 1; m <= 2; m <<= 1) {
            pn0 += __shfl_xor_sync(0xffffffffu, pn0, m);
            pq0 += __shfl_xor_sync(0xffffffffu, pq0, m);
            pk0 += __shfl_xor_sync(0xffffffffu, pk0, m);
            pn1 += __shfl_xor_sync(0xffffffffu, pn1, m);
            pq1 += __shfl_xor_sync(0xffffffffu, pq1, m);
            pk1 += __shfl_xor_sync(0xffffffffu, pk1, m);
        }
        if (t == 0) {
            int r = m0 + wm * 32 + mi * 16 + g;
            g_pnum[slot][r]     = pn0; g_pnq[slot][r]     = pq0; g_pnk[slot][r]     = pk0;
            g_pnum[slot][r + 8] = pn1; g_pnq[slot][r + 8] = pq1; g_pnk[slot][r + 8] = pk1;
        }
    }
}

// ============================ Kernel 2: finalize cos / p / flag ============================
__global__ __launch_bounds__(256)
void cosfin_kernel() {
    const int r = blockIdx.x * 256 + threadIdx.x;
    float num = 0.f, nq = 0.f, nk = 0.f;
    #pragma unroll
    for (int s = 0; s < 8; s++) {
        num += g_pnum[s][r]; nq += g_pnq[s][r]; nk += g_pnk[s][r];
    }
    const int l = r & (LSEQ - 1);
    float rs = rsqrtf(nq * nk);
    float cs = num * rs;
    float p = fminf(fmaxf(0.5f * (1.f - cs), 0.f), 1.f);
    if (l == 0) p = 1.f;
    g_p[r] = p;
    if (l != 0 && fabsf(cs) < 2e-4f) {
        int i = atomicAdd(&g_flag_cnt, 1);
        if (i < FLAG_CAP) { g_flagr[i] = r; g_flagrs[i] = rs; }
    }
}

// ============================ Kernel 3: exact num via M for flagged rows ============
// num = x_r^T M x_prev.  grid (2 d1-slices of 256, 128 chunk slots of 4 rows).
// Thread owns d1 = bx*256 + tid: y_j = M[d1,:]·x_prev_j, partial = x_r_j[d1]*y_j,
// deterministic block reduce -> g_fixp[bx][c0+j].
__global__ __launch_bounds__(256)
void fixm_kernel(const float* __restrict__ x) {
    __shared__ float4 xr[4][128], xp[4][128];
    __shared__ float  red[256];
    const int tid = threadIdx.x;
    const int d1  = blockIdx.x * 256 + tid;
    int cnt = g_flag_cnt; if (cnt > FLAG_CAP) cnt = FLAG_CAP;

    for (int c0 = blockIdx.y * 4; c0 < cnt; c0 += gridDim.y * 4) {
        const int nrows = min(4, cnt - c0);
        for (int idx = tid; idx < nrows * 128; idx += 256) {
            int j = idx >> 7, d4 = idx & 127;
            int r = g_flagr[c0 + j];              // l != 0 guaranteed
            xr[j][d4] = ((const float4*)(x + (size_t)r * D))[d4];
            xp[j][d4] = ((const float4*)(x + (size_t)(r - 1) * D))[d4];
        }
        __syncthreads();

        const float4* mrow = (const float4*)(g_M + (size_t)d1 * 512);
        float y0 = 0.f, y1 = 0.f, y2 = 0.f, y3 = 0.f;
        #pragma unroll 4
        for (int d4 = 0; d4 < 128; d4++) {
            float4 m = mrow[d4];
            float4 p0 = xp[0][d4]; y0 += m.x*p0.x + m.y*p0.y + m.z*p0.z + m.w*p0.w;
            float4 p1 = xp[1][d4]; y1 += m.x*p1.x + m.y*p1.y + m.z*p1.z + m.w*p1.w;
            float4 p2 = xp[2][d4]; y2 += m.x*p2.x + m.y*p2.y + m.z*p2.z + m.w*p2.w;
            float4 p3 = xp[3][d4]; y3 += m.x*p3.x + m.y*p3.y + m.z*p3.z + m.w*p3.w;
        }
        float yv[4] = {y0, y1, y2, y3};
        for (int j = 0; j < nrows; j++) {
            red[tid] = ((const float*)xr[j])[d1] * yv[j];
            __syncthreads();
            for (int o = 128; o > 0; o >>= 1) {
                if (tid < o) red[tid] += red[tid + o];
                __syncthreads();
            }
            if (tid == 0) g_fixp[blockIdx.x][c0 + j] = red[0];
            __syncthreads();
        }
        __syncthreads();
    }
}

// ============================ Kernel 3b: finalize fixed rows ============================
__global__ __launch_bounds__(256)
void fixfin_kernel() {
    int cnt = g_flag_cnt; if (cnt > FLAG_CAP) cnt = FLAG_CAP;
    for (int i = blockIdx.x * 256 + threadIdx.x; i < cnt; i += gridDim.x * 256) {
        float num = g_fixp[0][i] + g_fixp[1][i];
        g_p[g_flagr[i]] = fminf(fmaxf(0.5f * (1.f - num * g_flagrs[i]), 0.f), 1.f);
    }
}

// ============================ Kernel 4: per-batch scan ============================
__global__ __launch_bounds__(256)
void scan_kernel(float* __restrict__ out) {
    const int b   = blockIdx.x;
    const int tid = threadIdx.x;
    const int PER = LSEQ / 256;            // 32
    const int base = b * LSEQ + tid * PER;

    __shared__ int   sInt[256];
    __shared__ float sF[256];

    float pv[32];
    unsigned bits = 0;
    int localsum = 0;
    float psum = 0.f;

    #pragma unroll
    for (int u = 0; u < PER; u++) {
        int r = base + u;
        float p = g_p[r];
        pv[u] = p;
        int h = (p >= 0.5f) ? 1 : 0;
        bits |= ((unsigned)h) << u;
        localsum += h;
        psum += p;
    }

    sInt[tid] = localsum;
    __syncthreads();
    for (int off = 1; off < 256; off <<= 1) {
        int v = (tid >= off) ? sInt[tid - off] : 0;
        __syncthreads();
        sInt[tid] += v;
        __syncthreads();
    }
    int excl  = sInt[tid] - localsum;
    int total = sInt[255];

    int run = excl;
    #pragma unroll
    for (int u = 0; u < PER; u++) {
        int r = base + u;
        float p = pv[u];
        int h = (bits >> u) & 1;
        out[OFF_P  + r] = p;
        out[OFF_BH + r] = h ? 1.0f : 0.0f;
        g_pos[r] = h ? run : -1;
        run += h;
    }

    sF[tid] = psum;
    __syncthreads();
    for (int off = 128; off > 0; off >>= 1) {
        if (tid < off) sF[tid] += sF[tid + off];
        __syncthreads();
    }
    if (tid == 0) {
        g_cnt[b] = total;
        g_bsum[b * 2 + 0] = (float)total;
        g_bsum[b * 2 + 1] = sF[0];
    }
}

// ============================ Kernel 5: scatter ============================
__global__ __launch_bounds__(128)
void scatter_kernel(const float* __restrict__ x, float* __restrict__ out) {
    const int r   = blockIdx.x;
    const int b   = r >> 13;
    const int l   = r & (LSEQ - 1);
    const int tid = threadIdx.x;

    int pos = g_pos[r];
    if (pos >= 0) {
        float4 v = reinterpret_cast<const float4*>(x + (size_t)r * D)[tid];
        size_t dst = (size_t)(b * LSEQ + pos) * D;
        reinterpret_cast<float4*>(out + OFF_COMP + dst)[tid] = v;
        if (tid == 0) out[OFF_PC + b * LSEQ + pos] = out[OFF_P + r];
    }
    int cnt = g_cnt[b];
    if (l >= cnt) {
        reinterpret_cast<float4*>(out + OFF_COMP + (size_t)r * D)[tid] =
            make_float4(0.f, 0.f, 0.f, 0.f);
        if (tid == 0) { out[OFF_PC + r] = 0.f; out[OFF_MASK + r] = 0.f; }
    } else if (tid == 0) {
        out[OFF_MASK + r] = 1.0f;
    }
}

// ============================ Kernel 6: ratio loss ============================
__global__ void loss_kernel(float* __restrict__ out) {
    float F = 0.f, G = 0.f;
    for (int b = 0; b < BATCH; b++) { F += g_bsum[b*2+0]; G += g_bsum[b*2+1]; }
    F /= (float)NROWS;
    G /= (float)NROWS;
    const float N = 6.0f;
    out[OFF_LOSS] = N / (N - 1.0f) * ((N - 1.0f) * F * G + (1.0f - F) * (1.0f - G));
}

// ============================ launch ============================
extern "C" void kernel_launch(void* const* d_in, const int* in_sizes, int n_in,
                              void* d_out, int out_size) {
    const float* x  = (const float*)d_in[0];
    const float* Wq = (const float*)d_in[1];
    const float* Wk = (const float*)d_in[2];
    float* out = (float*)d_out;

    cudaFuncSetAttribute(gemm_fused_kernel, cudaFuncAttributeMaxDynamicSharedMemorySize, DYN_SMEM);

    zero_kernel<<<1, 1>>>();
    {
        dim3 mgrid(8, 8);
        mprep_kernel<<<mgrid, 256>>>(Wq, Wk);
    }
    {
        dim3 grid(4, 512);                                  // echunk x mtile
        gemm_fused_kernel<<<grid, 256, DYN_SMEM>>>(x, Wq, Wk);
    }
    cosfin_kernel<<<NROWS / 256, 256>>>();
    {
        dim3 fgrid(2, 128);                                 // d1-slice x chunk slot
        fixm_kernel<<<fgrid, 256>>>(x);
    }
    fixfin_kernel<<<32, 256>>>();
    scan_kernel<<<BATCH, 256>>>(out);
    scatter_kernel<<<NROWS, 128>>>(x, out);
    loss_kernel<<<1, 1>>>(out);
}

// round 13
// speedup vs baseline: 1.7782x; 1.1261x over previous
#include <cuda_runtime.h>
#include <cstdint>

#define D     512
#define LSEQ  8192
#define BATCH 8
#define NROWS (BATCH*LSEQ)   // 65536

// Output layout (float32, tuple order):
#define OFF_COMP 0ull
#define OFF_MASK 33554432ull            // B*L*D
#define OFF_BH   (OFF_MASK + 65536ull)
#define OFF_P    (OFF_BH   + 65536ull)
#define OFF_PC   (OFF_P    + 65536ull)
#define OFF_LOSS (OFF_PC   + 65536ull)

#define FLAG_CAP 8192

// GEMM tiling: KC=32, 3-stage
#define SA        36                  // smem row stride in floats (32 + 4 pad)
#define KC        32
#define NSTG      (D/KC)              // 16 k-stages
#define A_F       (129*SA)            // A tile: 129 rows (halo row m0-1)
#define B_F       (256*SA)            // B tile: Wq 128 rows + Wk 128 rows
#define SLOT_F    (A_F + B_F)         // 13860 floats
#define DYN_SMEM  (3*SLOT_F*4)        // 166320 bytes

// ---- scratch (static device arrays: no allocation) ----
__device__ float g_pnum[8][NROWS];    // per (echunk,wn) partial q·k_prev
__device__ float g_pnq [8][NROWS];    // partial |q|^2
__device__ float g_pnk [8][NROWS];    // partial |k_prev|^2
__device__ float g_M[512 * 512];      // Wq^T Wk  (1 MB, fp32 exact)
__device__ float g_p[NROWS];
__device__ int   g_pos[NROWS];
__device__ int   g_cnt[BATCH];
__device__ float g_bsum[BATCH * 2];
__device__ int   g_flag_cnt;
__device__ int   g_flagr[FLAG_CAP];
__device__ float g_flagrs[FLAG_CAP];
__device__ float g_fixp[2][FLAG_CAP];  // per-d1-slice exact partial of x_r^T M x_prev

// ============================ helpers ============================
__device__ __forceinline__ uint32_t smem_u32(const void* p) {
    uint32_t a;
    asm("{ .reg .u64 t; cvta.to.shared.u64 t, %1; cvt.u32.u64 %0, t; }" : "=r"(a) : "l"(p));
    return a;
}
__device__ __forceinline__ void cpasync16(uint32_t daddr, const void* gp) {
    asm volatile("cp.async.cg.shared.global [%0], [%1], 16;" :: "r"(daddr), "l"(gp) : "memory");
}
__device__ __forceinline__ void mma_tf32(float* c, const uint32_t* a, const uint32_t* b) {
    asm volatile(
        "mma.sync.aligned.m16n8k8.row.col.f32.tf32.tf32.f32 "
        "{%0,%1,%2,%3}, {%4,%5,%6,%7}, {%8,%9}, {%0,%1,%2,%3};"
        : "+f"(c[0]), "+f"(c[1]), "+f"(c[2]), "+f"(c[3])
        : "r"(a[0]), "r"(a[1]), "r"(a[2]), "r"(a[3]), "r"(b[0]), "r"(b[1]));
}

// ============================ Kernel 0: zero flag counter ============================
__global__ void zero_kernel() { g_flag_cnt = 0; }

// ============================ Kernel 0b: M = Wq^T Wk (fp32, tiled) ============================
__global__ __launch_bounds__(256)
void mprep_kernel(const float* __restrict__ Wq, const float* __restrict__ Wk) {
    __shared__ float sq[32][68], sk[32][68];
    const int tid = threadIdx.x;
    const int tx = tid & 15, ty = tid >> 4;
    const int d2_0 = blockIdx.x * 64, d1_0 = blockIdx.y * 64;

    float acc[4][4];
    #pragma unroll
    for (int i = 0; i < 4; i++)
        #pragma unroll
        for (int j = 0; j < 4; j++) acc[i][j] = 0.f;

    for (int e0 = 0; e0 < 512; e0 += 32) {
        #pragma unroll
        for (int it = 0; it < 2; it++) {
            int idx = it * 256 + tid;       // 0..511
            int i = idx >> 4, c4 = idx & 15;
            *(float4*)&sq[i][c4 * 4] = *(const float4*)&Wq[(size_t)(e0 + i) * D + d1_0 + c4 * 4];
            *(float4*)&sk[i][c4 * 4] = *(const float4*)&Wk[(size_t)(e0 + i) * D + d2_0 + c4 * 4];
        }
        __syncthreads();
        #pragma unroll
        for (int e = 0; e < 32; e++) {
            float4 av = *(const float4*)&sq[e][ty * 4];
            float4 bv = *(const float4*)&sk[e][tx * 4];
            float a[4] = {av.x, av.y, av.z, av.w};
            float b[4] = {bv.x, bv.y, bv.z, bv.w};
            #pragma unroll
            for (int i = 0; i < 4; i++)
                #pragma unroll
                for (int j = 0; j < 4; j++) acc[i][j] += a[i] * b[j];
        }
        __syncthreads();
    }
    #pragma unroll
    for (int i = 0; i < 4; i++) {
        float4 v = make_float4(acc[i][0], acc[i][1], acc[i][2], acc[i][3]);
        *(float4*)&g_M[(size_t)(d1_0 + ty * 4 + i) * 512 + d2_0 + tx * 4] = v;
    }
}

// ============================ Kernel 1: fused TF32 GEMM + row reductions ============
__global__ __launch_bounds__(256, 1)
void gemm_fused_kernel(const float* __restrict__ x,
                       const float* __restrict__ Wq,
                       const float* __restrict__ Wk) {
    extern __shared__ float sm[];
    const int tid  = threadIdx.x;
    const int w    = tid >> 5, lane = tid & 31;
    const int wm   = w >> 1, wn = w & 1;
    const int g    = lane >> 2, t = lane & 3;
    const int ec   = blockIdx.x;            // 0..3
    const int m0   = blockIdx.y * 128;
    const int e0   = ec * 128;

    float accq[2][8][4], acck[2][8][4];
    #pragma unroll
    for (int mi = 0; mi < 2; mi++)
        #pragma unroll
        for (int ni = 0; ni < 8; ni++)
            #pragma unroll
            for (int r = 0; r < 4; r++) { accq[mi][ni][r] = 0.f; acck[mi][ni][r] = 0.f; }

    const uint32_t smu = smem_u32(sm);

    auto issue = [&](int s, int slot) {
        const uint32_t sb = smu + (uint32_t)slot * SLOT_F * 4;
        const int k0 = s * KC;
        // A: 129 rows x 32 floats = 1032 float4
        #pragma unroll
        for (int it = 0; it < 5; it++) {
            int c = it * 256 + tid;
            if (c < 1032) {
                int row = c >> 3, c4 = c & 7;
                int gr = m0 - 1 + row; if (gr < 0) gr = 0;
                cpasync16(sb + (uint32_t)(row * SA + c4 * 4) * 4,
                          x + (size_t)gr * D + k0 + c4 * 4);
            }
        }
        // B: 256 rows x 32 floats = 2048 float4
        #pragma unroll
        for (int it = 0; it < 8; it++) {
            int c = it * 256 + tid;
            int row = c >> 3, c4 = c & 7;
            const float* src = (row < 128) ? (Wq + (size_t)(e0 + row) * D)
                                           : (Wk + (size_t)(e0 + row - 128) * D);
            cpasync16(sb + (uint32_t)(A_F + row * SA + c4 * 4) * 4,
                      src + k0 + c4 * 4);
        }
        asm volatile("cp.async.commit_group;" ::: "memory");
    };

    issue(0, 0);
    issue(1, 1);

    for (int s = 0; s < NSTG; s++) {
        if (s + 2 < NSTG) issue(s + 2, (s + 2) % 3);
        else asm volatile("cp.async.commit_group;" ::: "memory");
        asm volatile("cp.async.wait_group 2;" ::: "memory");
        __syncthreads();

        const float* As = sm + (s % 3) * SLOT_F;
        const float* Bs = As + A_F;

        #pragma unroll
        for (int k8 = 0; k8 < 4; k8++) {
            const int kk = k8 * 8;
            uint32_t aq[2][4], ak[2][4];
            #pragma unroll
            for (int mi = 0; mi < 2; mi++) {
                int r0 = wm * 32 + mi * 16 + g;          // local (row+1 = Q row)
                aq[mi][0] = __float_as_uint(As[(r0 + 1) * SA + kk + t    ]);
                aq[mi][1] = __float_as_uint(As[(r0 + 9) * SA + kk + t    ]);
                aq[mi][2] = __float_as_uint(As[(r0 + 1) * SA + kk + t + 4]);
                aq[mi][3] = __float_as_uint(As[(r0 + 9) * SA + kk + t + 4]);
                ak[mi][0] = __float_as_uint(As[(r0    ) * SA + kk + t    ]);
                ak[mi][1] = __float_as_uint(As[(r0 + 8) * SA + kk + t    ]);
                ak[mi][2] = __float_as_uint(As[(r0    ) * SA + kk + t + 4]);
                ak[mi][3] = __float_as_uint(As[(r0 + 8) * SA + kk + t + 4]);
            }
            uint32_t bq[8][2], bk[8][2];
            #pragma unroll
            for (int ni = 0; ni < 8; ni++) {
                int e = wn * 64 + ni * 8 + g;
                bq[ni][0] = __float_as_uint(Bs[(e      ) * SA + kk + t    ]);
                bq[ni][1] = __float_as_uint(Bs[(e      ) * SA + kk + t + 4]);
                bk[ni][0] = __float_as_uint(Bs[(128 + e) * SA + kk + t    ]);
                bk[ni][1] = __float_as_uint(Bs[(128 + e) * SA + kk + t + 4]);
            }
            #pragma unroll
            for (int mi = 0; mi < 2; mi++)
                #pragma unroll
                for (int ni = 0; ni < 8; ni++) {
                    mma_tf32(accq[mi][ni], aq[mi], bq[ni]);
                    mma_tf32(acck[mi][ni], ak[mi], bk[ni]);
                }
        }
        __syncthreads();
    }

    // Fused epilogue: per-row partial reductions over this warp's 64 cols.
    const int slot = ec * 2 + wn;
    #pragma unroll
    for (int mi = 0; mi < 2; mi++) {
        float pn0 = 0.f, pq0 = 0.f, pk0 = 0.f;
        float pn1 = 0.f, pq1 = 0.f, pk1 = 0.f;
        #pragma unroll
        for (int ni = 0; ni < 8; ni++) {
            float q0 = accq[mi][ni][0], q1 = accq[mi][ni][1];
            float q2 = accq[mi][ni][2], q3 = accq[mi][ni][3];
            float k0v = acck[mi][ni][0], k1v = acck[mi][ni][1];
            float k2v = acck[mi][ni][2], k3v = acck[mi][ni][3];
            pn0 += q0 * k0v + q1 * k1v;
            pq0 += q0 * q0 + q1 * q1;
            pk0 += k0v * k0v + k1v * k1v;
            pn1 += q2 * k2v + q3 * k3v;
            pq1 += q2 * q2 + q3 * q3;
            pk1 += k2v * k2v + k3v * k3v;
        }
        #pragma unroll
        for (int m = 1; m <= 2; m <<= 1) {
            pn0 += __shfl_xor_sync(0xffffffffu, pn0, m);
            pq0 += __shfl_xor_sync(0xffffffffu, pq0, m);
            pk0 += __shfl_xor_sync(0xffffffffu, pk0, m);
            pn1 += __shfl_xor_sync(0xffffffffu, pn1, m);
            pq1 += __shfl_xor_sync(0xffffffffu, pq1, m);
            pk1 += __shfl_xor_sync(0xffffffffu, pk1, m);
        }
        if (t == 0) {
            int r = m0 + wm * 32 + mi * 16 + g;
            g_pnum[slot][r]     = pn0; g_pnq[slot][r]     = pq0; g_pnk[slot][r]     = pk0;
            g_pnum[slot][r + 8] = pn1; g_pnq[slot][r + 8] = pq1; g_pnk[slot][r + 8] = pk1;
        }
    }
}

// ============================ Kernel 2: finalize cos / p / flag ============================
__global__ __launch_bounds__(256)
void cosfin_kernel() {
    const int r = blockIdx.x * 256 + threadIdx.x;
    float num = 0.f, nq = 0.f, nk = 0.f;
    #pragma unroll
    for (int s = 0; s < 8; s++) {
        num += g_pnum[s][r]; nq += g_pnq[s][r]; nk += g_pnk[s][r];
    }
    const int l = r & (LSEQ - 1);
    float rs = rsqrtf(nq * nk);
    float cs = num * rs;
    float p = fminf(fmaxf(0.5f * (1.f - cs), 0.f), 1.f);
    if (l == 0) p = 1.f;
    g_p[r] = p;
    if (l != 0 && fabsf(cs) < 2e-4f) {
        int i = atomicAdd(&g_flag_cnt, 1);
        if (i < FLAG_CAP) { g_flagr[i] = r; g_flagrs[i] = rs; }
    }
}

// ============================ Kernel 3: exact num via M for flagged rows ============
__global__ __launch_bounds__(256)
void fixm_kernel(const float* __restrict__ x) {
    __shared__ float4 xr[4][128], xp[4][128];
    __shared__ float  red[256];
    const int tid = threadIdx.x;
    const int d1  = blockIdx.x * 256 + tid;
    int cnt = g_flag_cnt; if (cnt > FLAG_CAP) cnt = FLAG_CAP;

    for (int c0 = blockIdx.y * 4; c0 < cnt; c0 += gridDim.y * 4) {
        const int nrows = min(4, cnt - c0);
        for (int idx = tid; idx < nrows * 128; idx += 256) {
            int j = idx >> 7, d4 = idx & 127;
            int r = g_flagr[c0 + j];              // l != 0 guaranteed
            xr[j][d4] = ((const float4*)(x + (size_t)r * D))[d4];
            xp[j][d4] = ((const float4*)(x + (size_t)(r - 1) * D))[d4];
        }
        __syncthreads();

        const float4* mrow = (const float4*)(g_M + (size_t)d1 * 512);
        float y0 = 0.f, y1 = 0.f, y2 = 0.f, y3 = 0.f;
        #pragma unroll 4
        for (int d4 = 0; d4 < 128; d4++) {
            float4 m = mrow[d4];
            float4 p0 = xp[0][d4]; y0 += m.x*p0.x + m.y*p0.y + m.z*p0.z + m.w*p0.w;
            float4 p1 = xp[1][d4]; y1 += m.x*p1.x + m.y*p1.y + m.z*p1.z + m.w*p1.w;
            float4 p2 = xp[2][d4]; y2 += m.x*p2.x + m.y*p2.y + m.z*p2.z + m.w*p2.w;
            float4 p3 = xp[3][d4]; y3 += m.x*p3.x + m.y*p3.y + m.z*p3.z + m.w*p3.w;
        }
        float yv[4] = {y0, y1, y2, y3};
        for (int j = 0; j < nrows; j++) {
            red[tid] = ((const float*)xr[j])[d1] * yv[j];
            __syncthreads();
            for (int o = 128; o > 0; o >>= 1) {
                if (tid < o) red[tid] += red[tid + o];
                __syncthreads();
            }
            if (tid == 0) g_fixp[blockIdx.x][c0 + j] = red[0];
            __syncthreads();
        }
        __syncthreads();
    }
}

// ============================ Kernel 3b: finalize fixed rows ============================
__global__ __launch_bounds__(256)
void fixfin_kernel() {
    int cnt = g_flag_cnt; if (cnt > FLAG_CAP) cnt = FLAG_CAP;
    for (int i = blockIdx.x * 256 + threadIdx.x; i < cnt; i += gridDim.x * 256) {
        float num = g_fixp[0][i] + g_fixp[1][i];
        g_p[g_flagr[i]] = fminf(fmaxf(0.5f * (1.f - num * g_flagrs[i]), 0.f), 1.f);
    }
}

// ============================ Kernel 4: per-batch scan ============================
__global__ __launch_bounds__(256)
void scan_kernel(float* __restrict__ out) {
    const int b   = blockIdx.x;
    const int tid = threadIdx.x;
    const int PER = LSEQ / 256;            // 32
    const int base = b * LSEQ + tid * PER;

    __shared__ int   sInt[256];
    __shared__ float sF[256];

    float pv[32];
    unsigned bits = 0;
    int localsum = 0;
    float psum = 0.f;

    #pragma unroll
    for (int u = 0; u < PER; u++) {
        int r = base + u;
        float p = g_p[r];
        pv[u] = p;
        int h = (p >= 0.5f) ? 1 : 0;
        bits |= ((unsigned)h) << u;
        localsum += h;
        psum += p;
    }

    sInt[tid] = localsum;
    __syncthreads();
    for (int off = 1; off < 256; off <<= 1) {
        int v = (tid >= off) ? sInt[tid - off] : 0;
        __syncthreads();
        sInt[tid] += v;
        __syncthreads();
    }
    int excl  = sInt[tid] - localsum;
    int total = sInt[255];

    int run = excl;
    #pragma unroll
    for (int u = 0; u < PER; u++) {
        int r = base + u;
        float p = pv[u];
        int h = (bits >> u) & 1;
        out[OFF_P  + r] = p;
        out[OFF_BH + r] = h ? 1.0f : 0.0f;
        g_pos[r] = h ? run : -1;
        run += h;
    }

    sF[tid] = psum;
    __syncthreads();
    for (int off = 128; off > 0; off >>= 1) {
        if (tid < off) sF[tid] += sF[tid + off];
        __syncthreads();
    }
    if (tid == 0) {
        g_cnt[b] = total;
        g_bsum[b * 2 + 0] = (float)total;
        g_bsum[b * 2 + 1] = sF[0];
    }
}

// ============================ Kernel 5: scatter ============================
__global__ __launch_bounds__(128)
void scatter_kernel(const float* __restrict__ x, float* __restrict__ out) {
    const int r   = blockIdx.x;
    const int b   = r >> 13;
    const int l   = r & (LSEQ - 1);
    const int tid = threadIdx.x;

    int pos = g_pos[r];
    if (pos >= 0) {
        float4 v = reinterpret_cast<const float4*>(x + (size_t)r * D)[tid];
        size_t dst = (size_t)(b * LSEQ + pos) * D;
        reinterpret_cast<float4*>(out + OFF_COMP + dst)[tid] = v;
        if (tid == 0) out[OFF_PC + b * LSEQ + pos] = out[OFF_P + r];
    }
    int cnt = g_cnt[b];
    if (l >= cnt) {
        reinterpret_cast<float4*>(out + OFF_COMP + (size_t)r * D)[tid] =
            make_float4(0.f, 0.f, 0.f, 0.f);
        if (tid == 0) { out[OFF_PC + r] = 0.f; out[OFF_MASK + r] = 0.f; }
    } else if (tid == 0) {
        out[OFF_MASK + r] = 1.0f;
    }
}

// ============================ Kernel 6: ratio loss ============================
__global__ void loss_kernel(float* __restrict__ out) {
    float F = 0.f, G = 0.f;
    for (int b = 0; b < BATCH; b++) { F += g_bsum[b*2+0]; G += g_bsum[b*2+1]; }
    F /= (float)NROWS;
    G /= (float)NROWS;
    const float N = 6.0f;
    out[OFF_LOSS] = N / (N - 1.0f) * ((N - 1.0f) * F * G + (1.0f - F) * (1.0f - G));
}

// ============================ launch ============================
extern "C" void kernel_launch(void* const* d_in, const int* in_sizes, int n_in,
                              void* d_out, int out_size) {
    const float* x  = (const float*)d_in[0];
    const float* Wq = (const float*)d_in[1];
    const float* Wk = (const float*)d_in[2];
    float* out = (float*)d_out;

    cudaFuncSetAttribute(gemm_fused_kernel, cudaFuncAttributeMaxDynamicSharedMemorySize, DYN_SMEM);

    zero_kernel<<<1, 1>>>();
    {
        dim3 mgrid(8, 8);
        mprep_kernel<<<mgrid, 256>>>(Wq, Wk);
    }
    {
        dim3 grid(4, 512);                                  // echunk x mtile
        gemm_fused_kernel<<<grid, 256, DYN_SMEM>>>(x, Wq, Wk);
    }
    cosfin_kernel<<<NROWS / 256, 256>>>();
    {
        dim3 fgrid(2, 128);                                 // d1-slice x chunk slot
        fixm_kernel<<<fgrid, 256>>>(x);
    }
    fixfin_kernel<<<32, 256>>>();
    scan_kernel<<<BATCH, 256>>>(out);
    scatter_kernel<<<NROWS, 128>>>(x, out);
    loss_kernel<<<1, 1>>>(out);
}